// round 8
// baseline (speedup 1.0000x reference)
#include <cuda_runtime.h>

// Problem constants: N=1024, DIM=201, G=200, R=72, C=4
#define NIMG  1024
#define DIMV  201
#define GG    200
#define RR    72
#define CC    4
#define RC    288          // R*C floats per channel (contiguous)
#define F4PC  72           // float4 per channel
#define BATCH 8            // channels per staged tile
#define NB    (GG / BATCH) // 25 batches
#define TILE_F4 (BATCH * F4PC)   // 576 float4 = 9216 B (2 cp.async per thread)
#define STAGES 3

// Scratch (device globals: allocation-free, graph-safe).
__device__ float        g_loss[NIMG];
__device__ unsigned int g_count = 0;   // reset by last block each run

__device__ __forceinline__ void cp_async16(unsigned dst, const void* src) {
    asm volatile("cp.async.cg.shared.global [%0], [%1], 16;\n"
                 :: "r"(dst), "l"(src) : "memory");
}
__device__ __forceinline__ void cp_commit() {
    asm volatile("cp.async.commit_group;\n" ::: "memory");
}
__device__ __forceinline__ void cp_wait1() {
    asm volatile("cp.async.wait_group 1;\n" ::: "memory");
}

// One block per image, 288 threads, 7 blocks/SM -> all 1024 blocks in ONE wave.
// 3-stage cp.async pipeline, 8 channels/tile; thread tid owns slot tid.
__global__ __launch_bounds__(RC, 7) void lane_loss_kernel(
    const float* __restrict__ x, const int* __restrict__ labels,
    float* __restrict__ out)
{
    __shared__ float s_tile[STAGES][TILE_F4 * 4];   // 3 x 9216 B
    __shared__ float s_pos[RC];
    __shared__ unsigned char s_valid[RC];
    __shared__ int   s_top[CC];
    __shared__ int   s_down[CC];
    __shared__ bool  s_last;

    const int n   = blockIdx.x;
    const int tid = threadIdx.x;

    // label validity: one coalesced load per thread
    s_valid[tid] = (labels[(size_t)n * RC + tid] < GG) ? 1 : 0;

    // ---- cp.async pipeline over 25 tiles of 8 channels ----
    const float4* xg = (const float4*)x + (size_t)n * (DIMV * F4PC);
    unsigned dstb[STAGES];
    #pragma unroll
    for (int st = 0; st < STAGES; ++st)
        dstb[st] = (unsigned)__cvta_generic_to_shared(&s_tile[st][0]) + tid * 16u;

    auto issue = [&](int b) {
        const float4* src = xg + b * TILE_F4 + tid;
        unsigned d = dstb[b % STAGES];
        cp_async16(d,              src);
        cp_async16(d + RC * 16u,   src + RC);
        cp_commit();
    };

    issue(0);
    issue(1);

    float s = 0.0f, p = 0.0f, gw = 0.0f;
    for (int b = 0; b < NB; ++b) {
        cp_wait1();            // tile b complete (<=1 group pending)
        __syncthreads();

        const float* t = &s_tile[b % STAGES][0] + tid;
        #pragma unroll
        for (int j = 0; j < BATCH; ++j) {
            float e = __expf(t[j * RC]);
            s += e;
            p  = fmaf(e, gw, p);
            gw += 1.0f;
        }
        __syncthreads();       // all consumed stage b%3 before reuse

        if (b + 2 < NB) issue(b + 2);
        else            cp_commit();   // keep group count in lockstep
    }

    s_pos[tid] = p / s;

    // ---- parse top/down per lane (threads 0..3, from smem) ----
    if (tid < CC) {
        int  top = 0, first_trans = -1;
        bool any_valid = false, prev = false;
        bool v0 = false, v1 = false, vlast = false;
        #pragma unroll
        for (int r = 0; r < RR; ++r) {
            bool v = (s_valid[r * CC + tid] != 0);
            if (v && !any_valid) { top = r; any_valid = true; }
            if (r > 0 && prev && !v && first_trans < 0) first_trans = r - 1;
            if (r == 0)      v0 = v;
            if (r == 1)      v1 = v;
            if (r == RR - 1) vlast = v;
            prev = v;
        }
        bool trans0 = v0 && !v1;
        int down = trans0 ? 0
                 : (vlast ? (RR - 1)
                 : (first_trans >= 0 ? first_trans : 0));
        if (!any_valid) { top = 0; down = 0; }
        s_top[tid]  = top;
        s_down[tid] = down;
    }
    __syncthreads();

    // ---- per-image loss: parallel over warp 0 ----
    if (tid < 32) {
        const int tl = max(s_top[0],  max(s_top[1],  s_top[2]));
        const int dl = min(s_down[0], min(s_down[1], s_down[2]));
        const int tr = max(s_top[1],  max(s_top[2],  s_top[3]));
        const int dr = min(s_down[1], min(s_down[2], s_down[3]));
        const bool al = (tl < dl);
        const bool ar = (tr < dr);

        float suml = 0.0f, sumr = 0.0f;
        const float4* pos4 = (const float4*)s_pos;
        #pragma unroll
        for (int k = 0; k < 3; ++k) {
            int r = tid + k * 32;
            if (r < RR) {
                float4 q = pos4[r];
                float ddl = fabsf(q.x - 2.0f * q.y + q.z);
                float ddr = fabsf(q.y - 2.0f * q.z + q.w);
                if (r >= tl && r <= dl) suml += ddl;
                if (r >= tr && r <= dr) sumr += ddr;
            }
        }
        #pragma unroll
        for (int o = 16; o > 0; o >>= 1) {
            suml += __shfl_down_sync(0xffffffffu, suml, o);
            sumr += __shfl_down_sync(0xffffffffu, sumr, o);
        }
        if (tid == 0) {
            float contrib = 0.0f;
            if (al) contrib += suml / (float)(dl - tl + 1);
            if (ar) contrib += sumr / (float)(dr - tr + 1);
            float denom = (al && ar) ? (2.0f * (float)RR) : (float)RR;
            g_loss[n] = contrib / denom;

            __threadfence();
            unsigned int old = atomicAdd(&g_count, 1u);
            s_last = (old == NIMG - 1);
        }
    }
    __syncthreads();

    // ---- last block: deterministic fixed-order global reduction ----
    if (s_last) {
        float sum = 0.0f;
        int   cnt = 0;
        #pragma unroll
        for (int k = 0; k < 4; ++k) {
            int i = tid + k * RC;            // covers 0..1151
            if (i < NIMG) {
                float v = g_loss[i];
                sum += v;
                cnt += (v != 0.0f) ? 1 : 0;
            }
        }
        #pragma unroll
        for (int o = 16; o > 0; o >>= 1) {
            sum += __shfl_down_sync(0xffffffffu, sum, o);
            cnt += __shfl_down_sync(0xffffffffu, cnt, o);
        }
        __shared__ float wsum[9];
        __shared__ int   wcnt[9];
        const int wid = tid >> 5, lid = tid & 31;
        if (lid == 0) { wsum[wid] = sum; wcnt[wid] = cnt; }
        __syncthreads();
        if (tid == 0) {
            float ts = 0.0f; int tc = 0;
            #pragma unroll
            for (int w = 0; w < 9; ++w) { ts += wsum[w]; tc += wcnt[w]; }
            out[0] = (tc > 0) ? (ts / (float)tc) : 0.0f;
            g_count = 0;   // reset for next graph replay
        }
    }
}

extern "C" void kernel_launch(void* const* d_in, const int* in_sizes, int n_in,
                              void* d_out, int out_size)
{
    const float* x      = (const float*)d_in[0];   // [1024, 201, 72, 4] f32
    const int*   labels = (const int*)d_in[1];     // [1024, 72, 4] int32
    float*       out    = (float*)d_out;           // scalar f32

    lane_loss_kernel<<<NIMG, RC>>>(x, labels, out);
}

// round 10
// speedup vs baseline: 1.0981x; 1.0981x over previous
#include <cuda_runtime.h>

// Problem constants: N=1024, DIM=201, G=200, R=72, C=4
#define NIMG 1024
#define DIMV 201
#define GG   200
#define RR   72
#define CC   4
#define RC   288    // R*C floats per channel (contiguous)
#define NIT  50     // iterations: 4 channels per iteration (50*4 = 200)

// Scratch (device globals: allocation-free, graph-safe).
__device__ float        g_loss[NIMG];
__device__ unsigned int g_count = 0;   // reset by last block each run

// One block per image, 288 threads, 7 blocks/SM -> all 1024 blocks in ONE wave.
// Sequential streaming: iteration i covers channels [4i, 4i+4) = float4s
// [i*288, (i+1)*288). Thread t loads float4 (i*288 + t): channel 4i + t/72,
// slots 4(t%72)..+3. Single-base immediate-offset LDG, weight = 4i immediate
// with residue q folded in at the end.
__global__ __launch_bounds__(RC, 7) void lane_loss_kernel(
    const float* __restrict__ x, const int* __restrict__ labels,
    float* __restrict__ out)
{
    __shared__ float sS[CC][RC];           // partial sum(exp) per residue q
    __shared__ float sP[CC][RC];           // partial sum(w*exp) per residue q
    __shared__ float s_pos[RC];            // row-major: s_pos[r*4+c]
    __shared__ unsigned char s_valid[RC];
    __shared__ int   s_top[CC];
    __shared__ int   s_down[CC];
    __shared__ bool  s_last;

    const int n   = blockIdx.x;
    const int tid = threadIdx.x;
    const int q   = tid / 72;         // channel residue class 0..3
    const int m   = tid % 72;         // float4 slot group 0..71

    // label validity: one coalesced load per thread
    s_valid[tid] = (labels[(size_t)n * RC + tid] < GG) ? 1 : 0;

    // ---- Phase 1: sequential-stream exp accumulation ----
    {
        const float4* xp = (const float4*)x + (size_t)n * (DIMV * 72) + tid;
        float s0 = 0.f, s1 = 0.f, s2 = 0.f, s3 = 0.f;
        float p0 = 0.f, p1 = 0.f, p2 = 0.f, p3 = 0.f;

        #pragma unroll
        for (int i = 0; i < NIT; ++i) {
            float4 v = __ldcs(xp + i * 288);       // 4-channel stride (1152 floats)
            const float w = (float)(4 * i);        // compile-time FFMA immediate
            float e0 = __expf(v.x), e1 = __expf(v.y);
            float e2 = __expf(v.z), e3 = __expf(v.w);
            s0 += e0; p0 = fmaf(e0, w, p0);
            s1 += e1; p1 = fmaf(e1, w, p1);
            s2 += e2; p2 = fmaf(e2, w, p2);
            s3 += e3; p3 = fmaf(e3, w, p3);
        }
        // fold in this thread's channel residue: true weight = 4i + q
        const float fq = (float)q;
        p0 = fmaf(fq, s0, p0);
        p1 = fmaf(fq, s1, p1);
        p2 = fmaf(fq, s2, p2);
        p3 = fmaf(fq, s3, p3);

        const int base = m * 4;
        sS[q][base + 0] = s0;  sP[q][base + 0] = p0;
        sS[q][base + 1] = s1;  sP[q][base + 1] = p1;
        sS[q][base + 2] = s2;  sP[q][base + 2] = p2;
        sS[q][base + 3] = s3;  sP[q][base + 3] = p3;
    }
    __syncthreads();

    // ---- combine residue partials -> pos; threads 0..3 scan validity ----
    {
        float s = sS[0][tid] + sS[1][tid] + sS[2][tid] + sS[3][tid];
        float p = sP[0][tid] + sP[1][tid] + sP[2][tid] + sP[3][tid];
        s_pos[tid] = p / s;
    }
    if (tid < CC) {
        int  top = 0, first_trans = -1;
        bool any_valid = false, prev = false;
        bool v0 = false, v1 = false, vlast = false;
        #pragma unroll
        for (int r = 0; r < RR; ++r) {
            bool v = (s_valid[r * CC + tid] != 0);
            if (v && !any_valid) { top = r; any_valid = true; }
            if (r > 0 && prev && !v && first_trans < 0) first_trans = r - 1;
            if (r == 0)      v0 = v;
            if (r == 1)      v1 = v;
            if (r == RR - 1) vlast = v;
            prev = v;
        }
        bool trans0 = v0 && !v1;
        int down = trans0 ? 0
                 : (vlast ? (RR - 1)
                 : (first_trans >= 0 ? first_trans : 0));
        if (!any_valid) { top = 0; down = 0; }
        s_top[tid]  = top;
        s_down[tid] = down;
    }
    __syncthreads();

    // ---- per-image loss: parallel over warp 0 ----
    if (tid < 32) {
        const int tl = max(s_top[0],  max(s_top[1],  s_top[2]));
        const int dl = min(s_down[0], min(s_down[1], s_down[2]));
        const int tr = max(s_top[1],  max(s_top[2],  s_top[3]));
        const int dr = min(s_down[1], min(s_down[2], s_down[3]));
        const bool al = (tl < dl);
        const bool ar = (tr < dr);

        float suml = 0.0f, sumr = 0.0f;
        const float4* pos4 = (const float4*)s_pos;
        #pragma unroll
        for (int k = 0; k < 3; ++k) {
            int r = tid + k * 32;
            if (r < RR) {
                float4 qv = pos4[r];
                float ddl = fabsf(qv.x - 2.0f * qv.y + qv.z);
                float ddr = fabsf(qv.y - 2.0f * qv.z + qv.w);
                if (r >= tl && r <= dl) suml += ddl;
                if (r >= tr && r <= dr) sumr += ddr;
            }
        }
        #pragma unroll
        for (int o = 16; o > 0; o >>= 1) {
            suml += __shfl_down_sync(0xffffffffu, suml, o);
            sumr += __shfl_down_sync(0xffffffffu, sumr, o);
        }
        if (tid == 0) {
            float contrib = 0.0f;
            if (al) contrib += suml / (float)(dl - tl + 1);
            if (ar) contrib += sumr / (float)(dr - tr + 1);
            float denom = (al && ar) ? (2.0f * (float)RR) : (float)RR;
            g_loss[n] = contrib / denom;

            __threadfence();
            unsigned int old = atomicAdd(&g_count, 1u);
            s_last = (old == NIMG - 1);
        }
    }
    __syncthreads();

    // ---- last block: deterministic fixed-order global reduction ----
    if (s_last) {
        float sum = 0.0f;
        int   cnt = 0;
        #pragma unroll
        for (int k = 0; k < 4; ++k) {
            int i = tid + k * RC;            // covers 0..1151
            if (i < NIMG) {
                float v = g_loss[i];
                sum += v;
                cnt += (v != 0.0f) ? 1 : 0;
            }
        }
        #pragma unroll
        for (int o = 16; o > 0; o >>= 1) {
            sum += __shfl_down_sync(0xffffffffu, sum, o);
            cnt += __shfl_down_sync(0xffffffffu, cnt, o);
        }
        __shared__ float wsum[9];
        __shared__ int   wcnt[9];
        const int wid = tid >> 5, lid = tid & 31;
        if (lid == 0) { wsum[wid] = sum; wcnt[wid] = cnt; }
        __syncthreads();
        if (tid == 0) {
            float ts = 0.0f; int tc = 0;
            #pragma unroll
            for (int w = 0; w < 9; ++w) { ts += wsum[w]; tc += wcnt[w]; }
            out[0] = (tc > 0) ? (ts / (float)tc) : 0.0f;
            g_count = 0;   // reset for next graph replay
        }
    }
}

extern "C" void kernel_launch(void* const* d_in, const int* in_sizes, int n_in,
                              void* d_out, int out_size)
{
    const float* x      = (const float*)d_in[0];   // [1024, 201, 72, 4] f32
    const int*   labels = (const int*)d_in[1];     // [1024, 72, 4] int32
    float*       out    = (float*)d_out;           // scalar f32

    lane_loss_kernel<<<NIMG, RC>>>(x, labels, out);
}

// round 11
// speedup vs baseline: 1.1404x; 1.0386x over previous
#include <cuda_runtime.h>

// Problem constants: N=1024, DIM=201, G=200, R=72, C=4
#define NIMG 1024
#define DIMV 201
#define GG   200
#define RR   72
#define CC   4
#define RC   288    // R*C floats per channel (contiguous)
#define NIT  50     // iterations: 4 channels per iteration (50*4 = 200)

// Scratch (device globals: allocation-free, graph-safe).
__device__ float        g_loss[NIMG];
__device__ unsigned int g_count = 0;   // reset by last block each run

// One block per image, 288 threads, 7 blocks/SM -> all 1024 blocks in ONE wave.
// Iteration i covers channels [4i,4i+4) = float4s [i*288,(i+1)*288); thread t
// loads float4 i*288+t (channel 4i + t/72, slots 4(t%72)..+3).
// Warp 0 parses labels via ballots in the head load-shadow (no barriers).
__global__ __launch_bounds__(RC, 7) void lane_loss_kernel(
    const float* __restrict__ x, const int* __restrict__ labels,
    float* __restrict__ out)
{
    __shared__ float sS[CC][RC];           // partial sum(exp) per residue q
    __shared__ float sP[CC][RC];           // partial sum(w*exp) per residue q
    __shared__ float s_pos[RC];            // row-major: s_pos[r*4+c]
    __shared__ int   s_top[CC];
    __shared__ int   s_down[CC];
    __shared__ bool  s_last;

    const int n   = blockIdx.x;
    const int tid = threadIdx.x;
    const int q   = tid / 72;         // channel residue class 0..3
    const int m   = tid % 72;         // float4 slot group 0..71

    // ---- head: warp 0 loads all labels + parses top/down (no barrier) ----
    if (tid < 32) {
        const int* lp = labels + (size_t)n * RC;
        unsigned bal[9];
        #pragma unroll
        for (int j = 0; j < 9; ++j)
            bal[j] = __ballot_sync(0xffffffffu, lp[j * 32 + tid] < GG);

        if (tid < CC) {
            // assemble 72-bit validity mask for column tid:
            // row 8w+k <- ballot w bit (4k + tid)
            unsigned long long lo = 0ull;   // rows 0..63
            unsigned hi = 0u;               // rows 64..71
            #pragma unroll
            for (int w = 0; w < 8; ++w) {
                #pragma unroll
                for (int k = 0; k < 8; ++k)
                    lo |= (unsigned long long)((bal[w] >> (4 * k + tid)) & 1u)
                          << (8 * w + k);
            }
            #pragma unroll
            for (int k = 0; k < 8; ++k)
                hi |= ((bal[8] >> (4 * k + tid)) & 1u) << k;

            const bool any = (lo | (unsigned long long)hi) != 0ull;
            int top;
            if (lo)      top = __ffsll((long long)lo) - 1;
            else if (hi) top = 64 + __ffs(hi) - 1;
            else         top = 0;

            // trans[r] = v[r] & !v[r+1], r in [0,70]
            unsigned long long sv  = (lo >> 1) | ((unsigned long long)(hi & 1u) << 63);
            unsigned long long tlo = lo & ~sv;
            unsigned           thi = hi & ~(hi >> 1) & 0x7Fu;
            int first_trans;
            const bool any_trans = (tlo != 0ull) || (thi != 0u);
            if (tlo)      first_trans = __ffsll((long long)tlo) - 1;
            else if (thi) first_trans = 64 + __ffs(thi) - 1;
            else          first_trans = 0;

            const bool v0    = (lo & 1ull) != 0ull;
            const bool v1    = ((lo >> 1) & 1ull) != 0ull;
            const bool vlast = ((hi >> 7) & 1u) != 0u;
            int down = (v0 && !v1) ? 0
                     : (vlast ? (RR - 1)
                     : (any_trans ? first_trans : 0));
            if (!any) { top = 0; down = 0; }
            s_top[tid]  = top;
            s_down[tid] = down;
        }
    }

    // ---- Phase 1: sequential-stream exp accumulation ----
    {
        const float4* xp = (const float4*)x + (size_t)n * (DIMV * 72) + tid;
        float s0 = 0.f, s1 = 0.f, s2 = 0.f, s3 = 0.f;
        float p0 = 0.f, p1 = 0.f, p2 = 0.f, p3 = 0.f;

        #pragma unroll
        for (int i = 0; i < NIT; ++i) {
            float4 v = xp[i * 288];                // 4-channel stride, default policy
            const float w = (float)(4 * i);        // compile-time FFMA immediate
            float e0 = __expf(v.x), e1 = __expf(v.y);
            float e2 = __expf(v.z), e3 = __expf(v.w);
            s0 += e0; p0 = fmaf(e0, w, p0);
            s1 += e1; p1 = fmaf(e1, w, p1);
            s2 += e2; p2 = fmaf(e2, w, p2);
            s3 += e3; p3 = fmaf(e3, w, p3);
        }
        // fold in this thread's channel residue: true weight = 4i + q
        const float fq = (float)q;
        p0 = fmaf(fq, s0, p0);
        p1 = fmaf(fq, s1, p1);
        p2 = fmaf(fq, s2, p2);
        p3 = fmaf(fq, s3, p3);

        const int base = m * 4;
        sS[q][base + 0] = s0;  sP[q][base + 0] = p0;
        sS[q][base + 1] = s1;  sP[q][base + 1] = p1;
        sS[q][base + 2] = s2;  sP[q][base + 2] = p2;
        sS[q][base + 3] = s3;  sP[q][base + 3] = p3;
    }
    __syncthreads();

    // ---- combine residue partials -> pos ----
    {
        float s = sS[0][tid] + sS[1][tid] + sS[2][tid] + sS[3][tid];
        float p = sP[0][tid] + sP[1][tid] + sP[2][tid] + sP[3][tid];
        s_pos[tid] = __fdividef(p, s);
    }
    __syncthreads();

    // ---- per-image loss: parallel over warp 0 ----
    if (tid < 32) {
        const int tl = max(s_top[0],  max(s_top[1],  s_top[2]));
        const int dl = min(s_down[0], min(s_down[1], s_down[2]));
        const int tr = max(s_top[1],  max(s_top[2],  s_top[3]));
        const int dr = min(s_down[1], min(s_down[2], s_down[3]));
        const bool al = (tl < dl);
        const bool ar = (tr < dr);

        float suml = 0.0f, sumr = 0.0f;
        const float4* pos4 = (const float4*)s_pos;
        #pragma unroll
        for (int k = 0; k < 3; ++k) {
            int r = tid + k * 32;
            if (r < RR) {
                float4 qv = pos4[r];
                float ddl = fabsf(qv.x - 2.0f * qv.y + qv.z);
                float ddr = fabsf(qv.y - 2.0f * qv.z + qv.w);
                if (r >= tl && r <= dl) suml += ddl;
                if (r >= tr && r <= dr) sumr += ddr;
            }
        }
        #pragma unroll
        for (int o = 16; o > 0; o >>= 1) {
            suml += __shfl_down_sync(0xffffffffu, suml, o);
            sumr += __shfl_down_sync(0xffffffffu, sumr, o);
        }
        if (tid == 0) {
            float contrib = 0.0f;
            if (al) contrib += suml / (float)(dl - tl + 1);
            if (ar) contrib += sumr / (float)(dr - tr + 1);
            float denom = (al && ar) ? (2.0f * (float)RR) : (float)RR;
            g_loss[n] = contrib / denom;

            __threadfence();
            unsigned int old = atomicAdd(&g_count, 1u);
            s_last = (old == NIMG - 1);
        }
    }
    __syncthreads();

    // ---- last block: deterministic fixed-order global reduction ----
    if (s_last) {
        float sum = 0.0f;
        int   cnt = 0;
        #pragma unroll
        for (int k = 0; k < 4; ++k) {
            int i = tid + k * RC;            // covers 0..1151
            if (i < NIMG) {
                float v = g_loss[i];
                sum += v;
                cnt += (v != 0.0f) ? 1 : 0;
            }
        }
        #pragma unroll
        for (int o = 16; o > 0; o >>= 1) {
            sum += __shfl_down_sync(0xffffffffu, sum, o);
            cnt += __shfl_down_sync(0xffffffffu, cnt, o);
        }
        __shared__ float wsum[9];
        __shared__ int   wcnt[9];
        const int wid = tid >> 5, lid = tid & 31;
        if (lid == 0) { wsum[wid] = sum; wcnt[wid] = cnt; }
        __syncthreads();
        if (tid == 0) {
            float ts = 0.0f; int tc = 0;
            #pragma unroll
            for (int w = 0; w < 9; ++w) { ts += wsum[w]; tc += wcnt[w]; }
            out[0] = (tc > 0) ? (ts / (float)tc) : 0.0f;
            g_count = 0;   // reset for next graph replay
        }
    }
}

extern "C" void kernel_launch(void* const* d_in, const int* in_sizes, int n_in,
                              void* d_out, int out_size)
{
    const float* x      = (const float*)d_in[0];   // [1024, 201, 72, 4] f32
    const int*   labels = (const int*)d_in[1];     // [1024, 72, 4] int32
    float*       out    = (float*)d_out;           // scalar f32

    lane_loss_kernel<<<NIMG, RC>>>(x, labels, out);
}